// round 7
// baseline (speedup 1.0000x reference)
#include <cuda_runtime.h>
#include <cuda_bf16.h>
#include <cstdint>
#include <math.h>

#define EDIM 256
#define NHEAD 8
#define HDIM 32
#define BATCH 4
#define LQ 512
#define LKV 4096
#define NLAYER 4
#define NTQ (LQ*BATCH)     // 2048 query tokens
#define NTKV (LKV*BATCH)   // 16384 kv tokens
#define NBH (BATCH*NHEAD)  // 32

// ---------------- scratch (device globals) ----------------
__device__ float g_x  [NTQ*EDIM];              // layer input [t,e], t = l*B+b
__device__ float g_kh [NBH*LKV*HDIM];          // K f32 [bh][kv][d]
__device__ float g_vh [NBH*LKV*HDIM];          // V f32 [bh][kv][d]
__device__ float g_t1 [NTQ*EDIM];
__device__ float g_x1 [NTQ*EDIM];
__device__ float g_t2 [NTQ*EDIM];
// pre-split packed bf16-pair buffers
__device__ uint32_t g_vsp_hi[NTKV*EDIM/2], g_vsp_lo[NTKV*EDIM/2];   // value activations (layer-invariant)
__device__ uint32_t g_xsp_hi[NTQ*EDIM/2],  g_xsp_lo[NTQ*EDIM/2];
__device__ uint32_t g_wsp_hi[3*EDIM*EDIM/2], g_wsp_lo[3*EDIM*EDIM/2];
__device__ uint32_t g_qsp_hi[NBH*LQ*16],   g_qsp_lo[NBH*LQ*16];     // Q pairs [bh][l][d/2]
__device__ uint32_t g_ksp_hi[NBH*LKV*16],  g_ksp_lo[NBH*LKV*16];    // K tiles [bh][tile][dpair][kv]
__device__ uint32_t g_vt_hi [NBH*LKV*16],  g_vt_lo [NBH*LKV*16];    // V tiles [bh][tile][kvpair][d]
__device__ uint32_t g_osp_hi[NTQ*128],     g_osp_lo[NTQ*128];       // attn out pairs [t][e/2]
__device__ uint32_t g_x1sp_hi[NTQ*128],    g_x1sp_lo[NTQ*128];
__device__ uint32_t g_hhsp_hi[NTQ*128],    g_hhsp_lo[NTQ*128];
__device__ uint32_t g_wosp_hi[EDIM*EDIM/2], g_wosp_lo[EDIM*EDIM/2];
__device__ uint32_t g_w1sp_hi[EDIM*EDIM/2], g_w1sp_lo[EDIM*EDIM/2];
__device__ uint32_t g_w2sp_hi[EDIM*EDIM/2], g_w2sp_lo[EDIM*EDIM/2];

__global__ void copy_kernel(const float* __restrict__ src, float* __restrict__ dst, int n){
    int i = blockIdx.x*blockDim.x + threadIdx.x;
    if (i < n) dst[i] = src[i];
}

// bf16 two-term split, packed pair (first elem in low 16 bits)
__device__ __forceinline__ void split_pack(float f0, float f1, uint32_t& hi, uint32_t& lo){
    __nv_bfloat16 h0 = __float2bfloat16_rn(f0);
    __nv_bfloat16 h1 = __float2bfloat16_rn(f1);
    __nv_bfloat16 l0 = __float2bfloat16_rn(f0 - __bfloat162float(h0));
    __nv_bfloat16 l1 = __float2bfloat16_rn(f1 - __bfloat162float(h1));
    hi = (uint32_t)__bfloat16_as_ushort(h0) | ((uint32_t)__bfloat16_as_ushort(h1) << 16);
    lo = (uint32_t)__bfloat16_as_ushort(l0) | ((uint32_t)__bfloat16_as_ushort(l1) << 16);
}

__global__ void split_kernel(const float* __restrict__ src, uint32_t* __restrict__ hi,
                             uint32_t* __restrict__ lo)
{
    int i = blockIdx.x*256 + threadIdx.x;
    float4 f = ((const float4*)src)[i];
    uint32_t h0,l0,h1,l1;
    split_pack(f.x, f.y, h0, l0);
    split_pack(f.z, f.w, h1, l1);
    ((uint2*)hi)[i] = make_uint2(h0, h1);
    ((uint2*)lo)[i] = make_uint2(l0, l1);
}

// repack K f32 [bh][kv][d] -> tiles [bh][kv/64][d/2][kv%64] packed pairs along d
__global__ void repack_k(const float* __restrict__ kf, uint32_t* __restrict__ khi,
                         uint32_t* __restrict__ klo)
{
    int i = blockIdx.x*256 + threadIdx.x;   // 0 .. NBH*LKV*16
    int bh  = i >> 16;
    int rem = i & 65535;
    int tile = rem >> 10;
    int p    = (rem >> 6) & 15;
    int kv   = rem & 63;
    const float* src = kf + ((size_t)bh*LKV + tile*64 + kv)*HDIM + p*2;
    uint32_t h, l;
    split_pack(src[0], src[1], h, l);
    khi[i] = h; klo[i] = l;
}

// repack V f32 [bh][kv][d] -> tiles [bh][kv/64][kvpair][d] packed pairs along kv
__global__ void repack_v(const float* __restrict__ vf, uint32_t* __restrict__ vhi,
                         uint32_t* __restrict__ vlo)
{
    int i = blockIdx.x*256 + threadIdx.x;
    int bh   = i >> 16;
    int tile = (i >> 10) & 63;
    int kp   = (i >> 5) & 31;
    int d    = i & 31;
    const float* src = vf + ((size_t)bh*LKV + tile*64 + kp*2)*HDIM + d;
    uint32_t h, l;
    split_pack(src[0], src[HDIM], h, l);
    vhi[i] = h; vlo[i] = l;
}

// mma.sync m16n8k16 row.col f32 += bf16*bf16
__device__ __forceinline__ void mma16816(float* d, const uint32_t* a, const uint32_t* b){
    asm volatile("mma.sync.aligned.m16n8k16.row.col.f32.bf16.bf16.f32 "
        "{%0,%1,%2,%3}, {%4,%5,%6,%7}, {%8,%9}, {%0,%1,%2,%3};"
        : "+f"(d[0]), "+f"(d[1]), "+f"(d[2]), "+f"(d[3])
        : "r"(a[0]), "r"(a[1]), "r"(a[2]), "r"(a[3]), "r"(b[0]), "r"(b[1]));
}

// ================= tc projection GEMM (pre-split operands) =================
// OUTM 0: rope+scale -> qsp pairs [bh][l][d/2]
// OUTM 2: (rope optional) -> f32 [bh][kv][d]
template<int OUTM, bool ROPE>
__global__ __launch_bounds__(256)
void gemm_rope_tc2(const uint32_t* __restrict__ Ahi, const uint32_t* __restrict__ Alo,
                   const uint32_t* __restrict__ Bhi, const uint32_t* __restrict__ Blo,
                   const float* __restrict__ bias, const float* __restrict__ pos,
                   uint32_t* __restrict__ ohi, uint32_t* __restrict__ olo,
                   float* __restrict__ of, int L, float scale)
{
    __shared__ uint32_t AS[2][16][136];
    __shared__ uint32_t BS[2][16][136];

    const int tid  = threadIdx.x;
    const int warp = tid >> 5;
    const int lane = tid & 31;
    const int g    = lane >> 2;
    const int tig  = lane & 3;
    const int wm   = warp >> 2;
    const int wn   = warp & 3;
    const int row0 = blockIdx.x * 128;
    const int col0 = blockIdx.y * 128;

    float acc[4][4][4];
#pragma unroll
    for (int i = 0; i < 4; i++)
#pragma unroll
        for (int n = 0; n < 4; n++)
#pragma unroll
            for (int x = 0; x < 4; x++) acc[i][n][x] = 0.f;

    const int r    = tid >> 1;
    const int kpb  = (tid & 1) * 8;

    for (int k0 = 0; k0 < EDIM; k0 += 32) {
        __syncthreads();
        {
            size_t aoff = (size_t)(row0 + r)*(EDIM/2) + (k0 >> 1) + kpb;
            size_t boff = (size_t)(col0 + r)*(EDIM/2) + (k0 >> 1) + kpb;
            uint4 a0 = *(const uint4*)(Ahi + aoff);
            uint4 a1 = *(const uint4*)(Ahi + aoff + 4);
            AS[0][kpb+0][r]=a0.x; AS[0][kpb+1][r]=a0.y; AS[0][kpb+2][r]=a0.z; AS[0][kpb+3][r]=a0.w;
            AS[0][kpb+4][r]=a1.x; AS[0][kpb+5][r]=a1.y; AS[0][kpb+6][r]=a1.z; AS[0][kpb+7][r]=a1.w;
            uint4 a2 = *(const uint4*)(Alo + aoff);
            uint4 a3 = *(const uint4*)(Alo + aoff + 4);
            AS[1][kpb+0][r]=a2.x; AS[1][kpb+1][r]=a2.y; AS[1][kpb+2][r]=a2.z; AS[1][kpb+3][r]=a2.w;
            AS[1][kpb+4][r]=a3.x; AS[1][kpb+5][r]=a3.y; AS[1][kpb+6][r]=a3.z; AS[1][kpb+7][r]=a3.w;
            uint4 b0 = *(const uint4*)(Bhi + boff);
            uint4 b1 = *(const uint4*)(Bhi + boff + 4);
            BS[0][kpb+0][r]=b0.x; BS[0][kpb+1][r]=b0.y; BS[0][kpb+2][r]=b0.z; BS[0][kpb+3][r]=b0.w;
            BS[0][kpb+4][r]=b1.x; BS[0][kpb+5][r]=b1.y; BS[0][kpb+6][r]=b1.z; BS[0][kpb+7][r]=b1.w;
            uint4 b2 = *(const uint4*)(Blo + boff);
            uint4 b3 = *(const uint4*)(Blo + boff + 4);
            BS[1][kpb+0][r]=b2.x; BS[1][kpb+1][r]=b2.y; BS[1][kpb+2][r]=b2.z; BS[1][kpb+3][r]=b2.w;
            BS[1][kpb+4][r]=b3.x; BS[1][kpb+5][r]=b3.y; BS[1][kpb+6][r]=b3.z; BS[1][kpb+7][r]=b3.w;
        }
        __syncthreads();

#pragma unroll
        for (int kc = 0; kc < 2; kc++) {
            uint32_t bh[4][2], bl[4][2];
#pragma unroll
            for (int n = 0; n < 4; n++) {
                int c = wn*32 + n*8 + g;
                bh[n][0] = BS[0][kc*8 + tig    ][c];
                bh[n][1] = BS[0][kc*8 + 4 + tig][c];
                bl[n][0] = BS[1][kc*8 + tig    ][c];
                bl[n][1] = BS[1][kc*8 + 4 + tig][c];
            }
#pragma unroll
            for (int i = 0; i < 4; i++) {
                uint32_t ah[4], al[4];
#pragma unroll
                for (int part = 0; part < 4; part++) {
                    int rr = wm*64 + i*16 + g + (part & 1)*8;
                    int kp = kc*8 + (part >> 1)*4 + tig;
                    ah[part] = AS[0][kp][rr];
                    al[part] = AS[1][kp][rr];
                }
#pragma unroll
                for (int n = 0; n < 4; n++) {
                    mma16816(acc[i][n], ah, bh[n]);
                    mma16816(acc[i][n], ah, bl[n]);
                    mma16816(acc[i][n], al, bh[n]);
                }
            }
        }
    }

#pragma unroll
    for (int i = 0; i < 4; i++) {
#pragma unroll
        for (int n = 0; n < 4; n++) {
            int c  = col0 + wn*32 + n*8 + tig*2;
            int h  = c >> 5;
            int d  = c & 31;
            float b0 = bias[c], b1 = bias[c+1];
#pragma unroll
            for (int hf = 0; hf < 2; hf++) {
                int t  = row0 + wm*64 + i*16 + g + hf*8;
                int l  = t >> 2;
                int bb = t & 3;
                float v0 = (acc[i][n][hf*2+0] + b0) * scale;
                float v1 = (acc[i][n][hf*2+1] + b1) * scale;
                if (ROPE) {
                    const float* pp = pos + ((size_t)(bb*L + l)*EDIM + c)*2;
                    float4 cs = *(const float4*)pp;
                    float ve = v0, vo = v1;
                    v0 = ve*cs.x - vo*cs.y;
                    v1 = vo*cs.z + ve*cs.w;
                }
                if (OUTM == 0) {
                    uint32_t ph, pl;
                    split_pack(v0, v1, ph, pl);
                    size_t idx = ((size_t)(bb*NHEAD + h)*L + l)*16 + (d >> 1);
                    ohi[idx] = ph; olo[idx] = pl;
                } else {
                    *(float2*)(of + ((size_t)(bb*NHEAD + h)*L + l)*HDIM + d) = make_float2(v0, v1);
                }
            }
        }
    }
}

// ================= tc generic GEMM (pre-split A/B) =================
// MODE 0: out_f32 = acc + bias + res
// MODE 1: relu(acc + bias) -> split pairs out
template<int MODE>
__global__ __launch_bounds__(256)
void gemm_tc_gen(const uint32_t* __restrict__ Ahi, const uint32_t* __restrict__ Alo,
                 const uint32_t* __restrict__ Bhi, const uint32_t* __restrict__ Blo,
                 const float* __restrict__ bias, const float* __restrict__ res,
                 float* __restrict__ outf, uint32_t* __restrict__ ohi, uint32_t* __restrict__ olo)
{
    __shared__ uint32_t AS[2][16][136];
    __shared__ uint32_t BS[2][16][136];

    const int tid  = threadIdx.x;
    const int warp = tid >> 5;
    const int lane = tid & 31;
    const int g    = lane >> 2;
    const int tig  = lane & 3;
    const int wm   = warp >> 2;
    const int wn   = warp & 3;
    const int row0 = blockIdx.x * 128;
    const int col0 = blockIdx.y * 128;

    float acc[4][4][4];
#pragma unroll
    for (int i = 0; i < 4; i++)
#pragma unroll
        for (int n = 0; n < 4; n++)
#pragma unroll
            for (int x = 0; x < 4; x++) acc[i][n][x] = 0.f;

    const int r   = tid >> 1;
    const int kpb = (tid & 1) * 8;

    for (int k0 = 0; k0 < EDIM; k0 += 32) {
        __syncthreads();
        {
            size_t aoff = (size_t)(row0 + r)*(EDIM/2) + (k0 >> 1) + kpb;
            size_t boff = (size_t)(col0 + r)*(EDIM/2) + (k0 >> 1) + kpb;
            uint4 a0 = *(const uint4*)(Ahi + aoff);
            uint4 a1 = *(const uint4*)(Ahi + aoff + 4);
            AS[0][kpb+0][r]=a0.x; AS[0][kpb+1][r]=a0.y; AS[0][kpb+2][r]=a0.z; AS[0][kpb+3][r]=a0.w;
            AS[0][kpb+4][r]=a1.x; AS[0][kpb+5][r]=a1.y; AS[0][kpb+6][r]=a1.z; AS[0][kpb+7][r]=a1.w;
            uint4 a2 = *(const uint4*)(Alo + aoff);
            uint4 a3 = *(const uint4*)(Alo + aoff + 4);
            AS[1][kpb+0][r]=a2.x; AS[1][kpb+1][r]=a2.y; AS[1][kpb+2][r]=a2.z; AS[1][kpb+3][r]=a2.w;
            AS[1][kpb+4][r]=a3.x; AS[1][kpb+5][r]=a3.y; AS[1][kpb+6][r]=a3.z; AS[1][kpb+7][r]=a3.w;
            uint4 b0 = *(const uint4*)(Bhi + boff);
            uint4 b1 = *(const uint4*)(Bhi + boff + 4);
            BS[0][kpb+0][r]=b0.x; BS[0][kpb+1][r]=b0.y; BS[0][kpb+2][r]=b0.z; BS[0][kpb+3][r]=b0.w;
            BS[0][kpb+4][r]=b1.x; BS[0][kpb+5][r]=b1.y; BS[0][kpb+6][r]=b1.z; BS[0][kpb+7][r]=b1.w;
            uint4 b2 = *(const uint4*)(Blo + boff);
            uint4 b3 = *(const uint4*)(Blo + boff + 4);
            BS[1][kpb+0][r]=b2.x; BS[1][kpb+1][r]=b2.y; BS[1][kpb+2][r]=b2.z; BS[1][kpb+3][r]=b2.w;
            BS[1][kpb+4][r]=b3.x; BS[1][kpb+5][r]=b3.y; BS[1][kpb+6][r]=b3.z; BS[1][kpb+7][r]=b3.w;
        }
        __syncthreads();

#pragma unroll
        for (int kc = 0; kc < 2; kc++) {
            uint32_t bh[4][2], bl[4][2];
#pragma unroll
            for (int n = 0; n < 4; n++) {
                int c = wn*32 + n*8 + g;
                bh[n][0] = BS[0][kc*8 + tig    ][c];
                bh[n][1] = BS[0][kc*8 + 4 + tig][c];
                bl[n][0] = BS[1][kc*8 + tig    ][c];
                bl[n][1] = BS[1][kc*8 + 4 + tig][c];
            }
#pragma unroll
            for (int i = 0; i < 4; i++) {
                uint32_t ah[4], al[4];
#pragma unroll
                for (int part = 0; part < 4; part++) {
                    int rr = wm*64 + i*16 + g + (part & 1)*8;
                    int kp = kc*8 + (part >> 1)*4 + tig;
                    ah[part] = AS[0][kp][rr];
                    al[part] = AS[1][kp][rr];
                }
#pragma unroll
                for (int n = 0; n < 4; n++) {
                    mma16816(acc[i][n], ah, bh[n]);
                    mma16816(acc[i][n], ah, bl[n]);
                    mma16816(acc[i][n], al, bh[n]);
                }
            }
        }
    }

#pragma unroll
    for (int i = 0; i < 4; i++) {
#pragma unroll
        for (int n = 0; n < 4; n++) {
            int c  = col0 + wn*32 + n*8 + tig*2;
            float b0 = bias[c], b1 = bias[c+1];
#pragma unroll
            for (int hf = 0; hf < 2; hf++) {
                int t = row0 + wm*64 + i*16 + g + hf*8;
                float v0 = acc[i][n][hf*2+0] + b0;
                float v1 = acc[i][n][hf*2+1] + b1;
                if (MODE == 0) {
                    float2 rr = *(const float2*)(res + (size_t)t*EDIM + c);
                    *(float2*)(outf + (size_t)t*EDIM + c) = make_float2(v0 + rr.x, v1 + rr.y);
                } else {
                    v0 = fmaxf(v0, 0.f);
                    v1 = fmaxf(v1, 0.f);
                    uint32_t ph, pl;
                    split_pack(v0, v1, ph, pl);
                    size_t idx = (size_t)t*128 + (c >> 1);
                    ohi[idx] = ph; olo[idx] = pl;
                }
            }
        }
    }
}

// ================= mma.sync flash attention (all operands pre-split) =================
__global__ __launch_bounds__(256)
void attn_mma2(const uint32_t* __restrict__ qhi, const uint32_t* __restrict__ qlo,
               const uint32_t* __restrict__ khi, const uint32_t* __restrict__ klo,
               const uint32_t* __restrict__ vhi, const uint32_t* __restrict__ vlo,
               uint32_t* __restrict__ ohi, uint32_t* __restrict__ olo)
{
    __shared__ uint32_t KSh[16][72], KSl[16][72];
    __shared__ uint32_t VSh[32][40], VSl[32][40];

    const int tid  = threadIdx.x;
    const int warp = tid >> 5;
    const int lane = tid & 31;
    const int g    = lane >> 2;
    const int tig  = lane & 3;
    const int bh   = blockIdx.y;
    const int q0   = blockIdx.x * 128;
    const int bb   = bh >> 3;
    const int hh   = bh & 7;

    // Q fragments from pre-split pairs
    uint32_t qa_hi[2][4], qa_lo[2][4];
#pragma unroll
    for (int kc = 0; kc < 2; kc++)
#pragma unroll
        for (int part = 0; part < 4; part++) {
            int r = q0 + warp*16 + g + (part & 1)*8;
            size_t idx = ((size_t)bh*LQ + r)*16 + kc*8 + (part >> 1)*4 + tig;
            qa_hi[kc][part] = qhi[idx];
            qa_lo[kc][part] = qlo[idx];
        }

    float oacc[4][4];
#pragma unroll
    for (int n = 0; n < 4; n++)
#pragma unroll
        for (int x = 0; x < 4; x++) oacc[n][x] = 0.f;
    float lsum0 = 0.f, lsum8 = 0.f;

    const int i0 = tid * 4;
    const int kp_ = i0 >> 6, kv_ = i0 & 63;    // K tile coords
    const int vp_ = i0 >> 5, vd_ = i0 & 31;    // V tile coords

    for (int tile = 0; tile < LKV/64; tile++) {
        __syncthreads();
        {
            size_t base = ((size_t)bh*(LKV/64) + tile) << 10;
            uint4 a = *(const uint4*)(khi + base + i0);
            KSh[kp_][kv_+0]=a.x; KSh[kp_][kv_+1]=a.y; KSh[kp_][kv_+2]=a.z; KSh[kp_][kv_+3]=a.w;
            uint4 b = *(const uint4*)(klo + base + i0);
            KSl[kp_][kv_+0]=b.x; KSl[kp_][kv_+1]=b.y; KSl[kp_][kv_+2]=b.z; KSl[kp_][kv_+3]=b.w;
            uint4 c = *(const uint4*)(vhi + base + i0);
            VSh[vp_][vd_+0]=c.x; VSh[vp_][vd_+1]=c.y; VSh[vp_][vd_+2]=c.z; VSh[vp_][vd_+3]=c.w;
            uint4 d = *(const uint4*)(vlo + base + i0);
            VSl[vp_][vd_+0]=d.x; VSl[vp_][vd_+1]=d.y; VSl[vp_][vd_+2]=d.z; VSl[vp_][vd_+3]=d.w;
        }
        __syncthreads();

        // S = Q K^T
        float sc[8][4];
#pragma unroll
        for (int j = 0; j < 8; j++)
#pragma unroll
            for (int x = 0; x < 4; x++) sc[j][x] = 0.f;
#pragma unroll
        for (int kc = 0; kc < 2; kc++) {
#pragma unroll
            for (int j = 0; j < 8; j++) {
                uint32_t bhf[2] = { KSh[kc*8+tig][j*8+g], KSh[kc*8+tig+4][j*8+g] };
                uint32_t blf[2] = { KSl[kc*8+tig][j*8+g], KSl[kc*8+tig+4][j*8+g] };
                mma16816(sc[j], qa_hi[kc], bhf);
                mma16816(sc[j], qa_hi[kc], blf);
                mma16816(sc[j], qa_lo[kc], bhf);
            }
        }

        // max-free softmax
#pragma unroll
        for (int j = 0; j < 8; j++) {
            sc[j][0] = __expf(sc[j][0]);
            sc[j][1] = __expf(sc[j][1]);
            sc[j][2] = __expf(sc[j][2]);
            sc[j][3] = __expf(sc[j][3]);
            lsum0 += sc[j][0] + sc[j][1];
            lsum8 += sc[j][2] + sc[j][3];
        }

        // O += P V
#pragma unroll
        for (int kc = 0; kc < 4; kc++) {
            uint32_t pa_hi[4], pa_lo[4];
            split_pack(sc[2*kc][0],   sc[2*kc][1],   pa_hi[0], pa_lo[0]);
            split_pack(sc[2*kc][2],   sc[2*kc][3],   pa_hi[1], pa_lo[1]);
            split_pack(sc[2*kc+1][0], sc[2*kc+1][1], pa_hi[2], pa_lo[2]);
            split_pack(sc[2*kc+1][2], sc[2*kc+1][3], pa_hi[3], pa_lo[3]);
#pragma unroll
            for (int n = 0; n < 4; n++) {
                uint32_t vh[2] = { VSh[kc*8+tig][n*8+g], VSh[kc*8+tig+4][n*8+g] };
                uint32_t vl[2] = { VSl[kc*8+tig][n*8+g], VSl[kc*8+tig+4][n*8+g] };
                mma16816(oacc[n], pa_hi, vh);
                mma16816(oacc[n], pa_hi, vl);
                mma16816(oacc[n], pa_lo, vh);
            }
        }
    }

    lsum0 += __shfl_xor_sync(0xffffffffu, lsum0, 1);
    lsum0 += __shfl_xor_sync(0xffffffffu, lsum0, 2);
    lsum8 += __shfl_xor_sync(0xffffffffu, lsum8, 1);
    lsum8 += __shfl_xor_sync(0xffffffffu, lsum8, 2);
    float inv0 = 1.f / lsum0;
    float inv8 = 1.f / lsum8;

    // write pre-split attention output pairs: osp[t][e/2], t = l*4+bb, e = hh*32 + d
#pragma unroll
    for (int n = 0; n < 4; n++) {
        int c = n*8 + tig*2;
        int epair = hh*16 + (c >> 1);
        int r0 = q0 + warp*16 + g;
        int t0 = r0*4 + bb;
        int t1 = (r0 + 8)*4 + bb;
        uint32_t ph, pl;
        split_pack(oacc[n][0]*inv0, oacc[n][1]*inv0, ph, pl);
        ohi[(size_t)t0*128 + epair] = ph; olo[(size_t)t0*128 + epair] = pl;
        split_pack(oacc[n][2]*inv8, oacc[n][3]*inv8, ph, pl);
        ohi[(size_t)t1*128 + epair] = ph; olo[(size_t)t1*128 + epair] = pl;
    }
}

// ---------------- layernorm ----------------
__global__ void ln_kernel(const float* __restrict__ x, const float* __restrict__ g,
                          const float* __restrict__ b, float* __restrict__ out1,
                          float* __restrict__ out2)
{
    __shared__ float red[8];
    const int t = blockIdx.x, e = threadIdx.x;
    const int w = e >> 5, lane = e & 31;
    float v = x[(size_t)t*EDIM + e];

    float s = v;
#pragma unroll
    for (int off = 16; off; off >>= 1) s += __shfl_xor_sync(0xffffffffu, s, off);
    if (lane == 0) red[w] = s;
    __syncthreads();
    if (e < 32) {
        float r = (lane < 8) ? red[lane] : 0.f;
#pragma unroll
        for (int off = 4; off; off >>= 1) r += __shfl_xor_sync(0xffffffffu, r, off, 8);
        if (lane == 0) red[0] = r;
    }
    __syncthreads();
    float mean = red[0] * (1.f/EDIM);
    __syncthreads();

    float dv = v - mean;
    float s2 = dv*dv;
#pragma unroll
    for (int off = 16; off; off >>= 1) s2 += __shfl_xor_sync(0xffffffffu, s2, off);
    if (lane == 0) red[w] = s2;
    __syncthreads();
    if (e < 32) {
        float r = (lane < 8) ? red[lane] : 0.f;
#pragma unroll
        for (int off = 4; off; off >>= 1) r += __shfl_xor_sync(0xffffffffu, r, off, 8);
        if (lane == 0) red[0] = r;
    }
    __syncthreads();
    float var = red[0] * (1.f/EDIM);

    float y = dv * rsqrtf(var + 1e-5f) * g[e] + b[e];
    out1[(size_t)t*EDIM + e] = y;
    if (out2) out2[(size_t)t*EDIM + e] = y;
}

// ---------------- launch ----------------
extern "C" void kernel_launch(void* const* d_in, const int* in_sizes, int n_in,
                              void* d_out, int out_size)
{
    (void)in_sizes; (void)n_in; (void)out_size;
    const float* query = (const float*)d_in[0];
    const float* value = (const float*)d_in[1];
    const float* qpos  = (const float*)d_in[2];
    const float* vpos  = (const float*)d_in[3];
    const float* Wqkv  = (const float*)d_in[4];
    const float* bqkv  = (const float*)d_in[5];
    const float* Wo    = (const float*)d_in[6];
    const float* bo    = (const float*)d_in[7];
    const float* ln1g  = (const float*)d_in[8];
    const float* ln1b  = (const float*)d_in[9];
    const float* W1    = (const float*)d_in[10];
    const float* b1    = (const float*)d_in[11];
    const float* W2    = (const float*)d_in[12];
    const float* b2    = (const float*)d_in[13];
    const float* ln2g  = (const float*)d_in[14];
    const float* ln2b  = (const float*)d_in[15];
    float* out = (float*)d_out;

#define GETSYM(var, sym, type) void* var##_; cudaGetSymbolAddress(&var##_, sym); type* var = (type*)var##_
    GETSYM(px,   g_x,   float);
    GETSYM(pkh,  g_kh,  float);
    GETSYM(pvh,  g_vh,  float);
    GETSYM(pt1,  g_t1,  float);
    GETSYM(px1,  g_x1,  float);
    GETSYM(pt2,  g_t2,  float);
    GETSYM(vsp_hi, g_vsp_hi, uint32_t);  GETSYM(vsp_lo, g_vsp_lo, uint32_t);
    GETSYM(xsp_hi, g_xsp_hi, uint32_t);  GETSYM(xsp_lo, g_xsp_lo, uint32_t);
    GETSYM(wsp_hi, g_wsp_hi, uint32_t);  GETSYM(wsp_lo, g_wsp_lo, uint32_t);
    GETSYM(qsp_hi, g_qsp_hi, uint32_t);  GETSYM(qsp_lo, g_qsp_lo, uint32_t);
    GETSYM(ksp_hi, g_ksp_hi, uint32_t);  GETSYM(ksp_lo, g_ksp_lo, uint32_t);
    GETSYM(vt_hi,  g_vt_hi,  uint32_t);  GETSYM(vt_lo,  g_vt_lo,  uint32_t);
    GETSYM(osp_hi, g_osp_hi, uint32_t);  GETSYM(osp_lo, g_osp_lo, uint32_t);
    GETSYM(x1sp_hi, g_x1sp_hi, uint32_t); GETSYM(x1sp_lo, g_x1sp_lo, uint32_t);
    GETSYM(hhsp_hi, g_hhsp_hi, uint32_t); GETSYM(hhsp_lo, g_hhsp_lo, uint32_t);
    GETSYM(wosp_hi, g_wosp_hi, uint32_t); GETSYM(wosp_lo, g_wosp_lo, uint32_t);
    GETSYM(w1sp_hi, g_w1sp_hi, uint32_t); GETSYM(w1sp_lo, g_w1sp_lo, uint32_t);
    GETSYM(w2sp_hi, g_w2sp_hi, uint32_t); GETSYM(w2sp_lo, g_w2sp_lo, uint32_t);
#undef GETSYM

    copy_kernel<<<NTQ*EDIM/256, 256>>>(query, px, NTQ*EDIM);
    split_kernel<<<NTKV*EDIM/4/256, 256>>>(value, vsp_hi, vsp_lo);   // once: layer-invariant

    const float scale = 0.17677669529663687f;  // 1/sqrt(32)
    for (int l = 0; l < NLAYER; l++) {
        const float* Wq = Wqkv + (size_t)l*3*EDIM*EDIM;
        const float* bq = bqkv + (size_t)l*3*EDIM;
        const float* bk = bq + EDIM;
        const float* bv = bq + 2*EDIM;

        split_kernel<<<NTQ*EDIM/4/256, 256>>>(px, xsp_hi, xsp_lo);
        split_kernel<<<3*EDIM*EDIM/4/256, 256>>>(Wq, wsp_hi, wsp_lo);

        // projections
        gemm_rope_tc2<0,true ><<<dim3(NTQ/128,  2), 256>>>(xsp_hi, xsp_lo, wsp_hi, wsp_lo,
            bq, qpos, qsp_hi, qsp_lo, nullptr, LQ, scale);
        gemm_rope_tc2<2,true ><<<dim3(NTKV/128, 2), 256>>>(vsp_hi, vsp_lo, wsp_hi + EDIM*EDIM/2, wsp_lo + EDIM*EDIM/2,
            bk, vpos, nullptr, nullptr, pkh, LKV, 1.0f);
        gemm_rope_tc2<2,false><<<dim3(NTKV/128, 2), 256>>>(vsp_hi, vsp_lo, wsp_hi + EDIM*EDIM,  wsp_lo + EDIM*EDIM,
            bv, nullptr, nullptr, nullptr, pvh, LKV, 1.0f);

        repack_k<<<NBH*LKV*16/256, 256>>>(pkh, ksp_hi, ksp_lo);
        repack_v<<<NBH*LKV*16/256, 256>>>(pvh, vt_hi, vt_lo);

        attn_mma2<<<dim3(LQ/128, NBH), 256>>>(qsp_hi, qsp_lo, ksp_hi, ksp_lo, vt_hi, vt_lo,
                                              osp_hi, osp_lo);

        // Wo + residual
        split_kernel<<<EDIM*EDIM/4/256, 256>>>(Wo + (size_t)l*EDIM*EDIM, wosp_hi, wosp_lo);
        gemm_tc_gen<0><<<dim3(NTQ/128, 2), 256>>>(osp_hi, osp_lo, wosp_hi, wosp_lo,
            bo + l*EDIM, px, pt1, nullptr, nullptr);
        ln_kernel<<<NTQ, 256>>>(pt1, ln1g + l*EDIM, ln1b + l*EDIM, px1, nullptr);

        // FFN
        split_kernel<<<NTQ*EDIM/4/256, 256>>>(px1, x1sp_hi, x1sp_lo);
        split_kernel<<<EDIM*EDIM/4/256, 256>>>(W1 + (size_t)l*EDIM*EDIM, w1sp_hi, w1sp_lo);
        gemm_tc_gen<1><<<dim3(NTQ/128, 2), 256>>>(x1sp_hi, x1sp_lo, w1sp_hi, w1sp_lo,
            b1 + l*EDIM, nullptr, nullptr, hhsp_hi, hhsp_lo);
        split_kernel<<<EDIM*EDIM/4/256, 256>>>(W2 + (size_t)l*EDIM*EDIM, w2sp_hi, w2sp_lo);
        gemm_tc_gen<0><<<dim3(NTQ/128, 2), 256>>>(hhsp_hi, hhsp_lo, w2sp_hi, w2sp_lo,
            b2 + l*EDIM, px1, pt2, nullptr, nullptr);

        ln_kernel<<<NTQ, 256>>>(pt2, ln2g + l*EDIM, ln2b + l*EDIM, px, out + (size_t)l*NTQ*EDIM);
    }
}